// round 13
// baseline (speedup 1.0000x reference)
#include <cuda_runtime.h>

// FINAL — best-measured configuration, reconfirmed 3x on identical source:
//   bench 25.06 / 25.31 / 25.09 us ;  ncu 23.46 / 23.36 / 24.29 us
//   DRAM 74.6 / 74.8 / 72.0 %  (HBM 5.69-5.92 TB/s)  — run-to-run noise band.
//
// out[b] = sum_i cos(x[b,i]) * w[i] + bias ;  x: [1048576, 32] f32.
// theta input is mathematically dead (RZ phase leaves <Z> unchanged).
//
// One-shot warps: each warp processes exactly ONE batch of 4 groups
// (4 rows/group * 4 groups = 16 rows = 2KB), with 4 independent front-batched
// LDG.128 (MLP=4, __ldcs evict-first), then reduces and exits. Grid = 8192
// blocks (~7 waves) so the CTA scheduler continuously load-balances and the
// kernel tail is one 2KB batch.
//
// Falsified alternatives (DRAM%): single-wave persistent 71.1, MLP=8-in-regs
// 71.8, cp.async SMEM staging 67.7, LDG.256 65.3, 128-thr blocks 73.9,
// 16-group loops (w/ and w/o SW pipeline) 73.1-73.6.
//
// Lane l holds float4 #l of a 512B group; chunk = l&7 selects the weight quad;
// 3-step shfl_xor within each 8-lane subgroup yields the 4 row sums.

__device__ __forceinline__ float group_dot(const float4& xv, const float4& wv)
{
    return __cosf(xv.x) * wv.x + __cosf(xv.y) * wv.y
         + __cosf(xv.z) * wv.z + __cosf(xv.w) * wv.w;
}

__device__ __forceinline__ float reduce8(float s)
{
    s += __shfl_xor_sync(0xffffffffu, s, 1);
    s += __shfl_xor_sync(0xffffffffu, s, 2);
    s += __shfl_xor_sync(0xffffffffu, s, 4);
    return s;
}

__global__ void __launch_bounds__(256, 8) hybrid_regression_kernel(
    const float4* __restrict__ x4,
    const float*  __restrict__ w,
    const float*  __restrict__ bias,
    float*        __restrict__ out,
    int ngroups)
{
    int gtid  = blockIdx.x * blockDim.x + threadIdx.x;
    int warp  = gtid >> 5;
    int lane  = gtid & 31;
    int chunk = lane & 7;
    int sub   = lane >> 3;

    int g0 = warp * 4;                      // 4 groups per warp, one shot
    if (g0 >= ngroups) return;

    float4 wv = reinterpret_cast<const float4*>(w)[chunk];

    const float4* p = x4 + (size_t)g0 * 32 + lane;

    if (g0 + 4 <= ngroups) {
        // 4 independent coalesced 512B loads, front-batched (MLP=4)
        float4 xv0 = __ldcs(p +  0);
        float4 xv1 = __ldcs(p + 32);
        float4 xv2 = __ldcs(p + 64);
        float4 xv3 = __ldcs(p + 96);

        float bb = bias[0];

        float s0 = reduce8(group_dot(xv0, wv));
        float s1 = reduce8(group_dot(xv1, wv));
        float s2 = reduce8(group_dot(xv2, wv));
        float s3 = reduce8(group_dot(xv3, wv));

        if (chunk == 0) {
            int r = g0 * 4 + sub;
            out[r +  0] = s0 + bb;
            out[r +  4] = s1 + bb;
            out[r +  8] = s2 + bb;
            out[r + 12] = s3 + bb;
        }
    } else {
        // tail (not hit for B=1048576, kept for generality)
        float bb = bias[0];
        for (int g = g0; g < ngroups; ++g) {
            float4 xv = __ldcs(x4 + (size_t)g * 32 + lane);
            float s = reduce8(group_dot(xv, wv));
            if (chunk == 0) out[g * 4 + sub] = s + bb;
        }
    }
}

extern "C" void kernel_launch(void* const* d_in, const int* in_sizes, int n_in,
                              void* d_out, int out_size)
{
    const float* x    = (const float*)d_in[0];   // [B, 32]
    // d_in[1] = theta: mathematically dead (RZ phase leaves <Z> unchanged)
    const float* w    = (const float*)d_in[2];   // [1, 32]
    const float* b    = (const float*)d_in[3];   // [1]
    float* out        = (float*)d_out;

    int batch   = in_sizes[0] / 32;
    int ngroups = batch / 4;                      // 262144

    int threads = 256;
    int warps_per_block   = threads / 32;         // 8
    int groups_per_block  = warps_per_block * 4;  // 32
    int blocks = (ngroups + groups_per_block - 1) / groups_per_block;  // 8192

    hybrid_regression_kernel<<<blocks, threads>>>(
        (const float4*)x, w, b, out, ngroups);
}

// round 14
// speedup vs baseline: 1.0889x; 1.0889x over previous
#include <cuda_runtime.h>

// One-shot warps, 512-thread blocks (final point on the block-size curve;
// body identical to the 4x-confirmed best config):
//   128thr/16384blk -> ncu 23.71 ;  256thr/8192blk -> ncu 23.36-23.46 ;
//   512thr/4096blk  -> this probe.
//
// out[b] = sum_i cos(x[b,i]) * w[i] + bias ;  x: [1048576, 32] f32.
// theta input is mathematically dead (RZ phase leaves <Z> unchanged).
//
// Each warp processes exactly ONE batch of 4 groups (16 rows = 2KB) with 4
// independent front-batched LDG.128 (MLP=4, __ldcs), reduces, stores, exits.
// Lane l holds float4 #l of a 512B group; chunk = l&7 selects the weight quad;
// 3-step shfl_xor within each 8-lane subgroup yields the 4 row sums.

__device__ __forceinline__ float group_dot(const float4& xv, const float4& wv)
{
    return __cosf(xv.x) * wv.x + __cosf(xv.y) * wv.y
         + __cosf(xv.z) * wv.z + __cosf(xv.w) * wv.w;
}

__device__ __forceinline__ float reduce8(float s)
{
    s += __shfl_xor_sync(0xffffffffu, s, 1);
    s += __shfl_xor_sync(0xffffffffu, s, 2);
    s += __shfl_xor_sync(0xffffffffu, s, 4);
    return s;
}

__global__ void __launch_bounds__(512, 4) hybrid_regression_kernel(
    const float4* __restrict__ x4,
    const float*  __restrict__ w,
    const float*  __restrict__ bias,
    float*        __restrict__ out,
    int ngroups)
{
    int gtid  = blockIdx.x * blockDim.x + threadIdx.x;
    int warp  = gtid >> 5;
    int lane  = gtid & 31;
    int chunk = lane & 7;
    int sub   = lane >> 3;

    int g0 = warp * 4;                      // 4 groups per warp, one shot
    if (g0 >= ngroups) return;

    float4 wv = reinterpret_cast<const float4*>(w)[chunk];

    const float4* p = x4 + (size_t)g0 * 32 + lane;

    if (g0 + 4 <= ngroups) {
        // 4 independent coalesced 512B loads, front-batched (MLP=4)
        float4 xv0 = __ldcs(p +  0);
        float4 xv1 = __ldcs(p + 32);
        float4 xv2 = __ldcs(p + 64);
        float4 xv3 = __ldcs(p + 96);

        float bb = bias[0];

        float s0 = reduce8(group_dot(xv0, wv));
        float s1 = reduce8(group_dot(xv1, wv));
        float s2 = reduce8(group_dot(xv2, wv));
        float s3 = reduce8(group_dot(xv3, wv));

        if (chunk == 0) {
            int r = g0 * 4 + sub;
            out[r +  0] = s0 + bb;
            out[r +  4] = s1 + bb;
            out[r +  8] = s2 + bb;
            out[r + 12] = s3 + bb;
        }
    } else {
        // tail (not hit for B=1048576, kept for generality)
        float bb = bias[0];
        for (int g = g0; g < ngroups; ++g) {
            float4 xv = __ldcs(x4 + (size_t)g * 32 + lane);
            float s = reduce8(group_dot(xv, wv));
            if (chunk == 0) out[g * 4 + sub] = s + bb;
        }
    }
}

extern "C" void kernel_launch(void* const* d_in, const int* in_sizes, int n_in,
                              void* d_out, int out_size)
{
    const float* x    = (const float*)d_in[0];   // [B, 32]
    // d_in[1] = theta: mathematically dead (RZ phase leaves <Z> unchanged)
    const float* w    = (const float*)d_in[2];   // [1, 32]
    const float* b    = (const float*)d_in[3];   // [1]
    float* out        = (float*)d_out;

    int batch   = in_sizes[0] / 32;
    int ngroups = batch / 4;                      // 262144

    int threads = 512;
    int warps_per_block   = threads / 32;         // 16
    int groups_per_block  = warps_per_block * 4;  // 64
    int blocks = (ngroups + groups_per_block - 1) / groups_per_block;  // 4096

    hybrid_regression_kernel<<<blocks, threads>>>(
        (const float4*)x, w, b, out, ngroups);
}